// round 12
// baseline (speedup 1.0000x reference)
#include <cuda_runtime.h>
#include <cstdint>

// ---------------------------------------------------------------------------
// QuerySHLayerDeprecated: per-edge spherical harmonics (lmax=2) + smooth
// finite radial embedding (10 basis).
//
// Inputs (metadata order):
//   d_in[0] pos        float32 [100000, 3]
//   d_in[1] query_pos  float32 [8, 1250, 3]  (flattened to [10000, 3])
//   d_in[2] edge_src   int32   [E]  (indexes query rows)
//   d_in[3] edge_dst   int32   [E]  (indexes pos rows)
// Output: concat(edge_sh [E,9], edge_length_embedded [E,10]) as float32.
// ---------------------------------------------------------------------------

#define Q_CAP   10000
#define POS_CAP 100000

// Padded gather tables (float4 rows -> 1 LDG / 1 L2 sector per gather).
static __device__ float4 g_q4[Q_CAP];
static __device__ float4 g_pos4[POS_CAP];

__global__ void pad_q_kernel(const float* __restrict__ s, int rows) {
    int i = blockIdx.x * blockDim.x + threadIdx.x;
    if (i < rows) g_q4[i] = make_float4(s[3*i+0], s[3*i+1], s[3*i+2], 0.0f);
}
__global__ void pad_pos_kernel(const float* __restrict__ s, int rows) {
    int i = blockIdx.x * blockDim.x + threadIdx.x;
    if (i < rows) g_pos4[i] = make_float4(s[3*i+0], s[3*i+1], s[3*i+2], 0.0f);
}

template<bool PAD>
__global__ __launch_bounds__(256, 8)
void edge_kernel(const float* __restrict__ qraw, const float* __restrict__ praw,
                 const int* __restrict__ esrc, const int* __restrict__ edst,
                 float* __restrict__ out_sh, float* __restrict__ out_emb, int n)
{
    const float SQRT3      = 1.7320508075688772f;
    const float HALF_SQRT3 = 0.8660254037844386f;
    // 1.14136 * e^2 * sqrt(10)
    const float PREF = 1.14136f * 7.389056098930650f * 3.1622776601683795f;

    // Per-warp staging buffers for coalesced output stores.
    __shared__ float ssh [8][9 * 32];       // stride 9: gcd(9,32)=1, conflict-free
    __shared__ float semb[8][11 * 32];      // padded stride 11: conflict-free writes

    const int tid  = threadIdx.x;
    const int lane = tid & 31;
    const int w    = tid >> 5;
    const int e    = blockIdx.x * 256 + tid;
    const bool valid = e < n;

    float ax = 0.f, ay = 0.f, az = 0.f, bx = 0.f, by = 0.f, bz = 0.f;
    if (valid) {
        int s = __ldg(esrc + e);
        int d = __ldg(edst + e);
        if (PAD) {
            float4 a = __ldg(&g_q4[s]);
            float4 b = __ldg(&g_pos4[d]);
            ax = a.x; ay = a.y; az = a.z;
            bx = b.x; by = b.y; bz = b.z;
        } else {
            ax = __ldg(qraw + 3*s);  ay = __ldg(qraw + 3*s + 1); az = __ldg(qraw + 3*s + 2);
            bx = __ldg(praw + 3*d);  by = __ldg(praw + 3*d + 1); bz = __ldg(praw + 3*d + 2);
        }
    }

    const float x = ax - bx, y = ay - by, z = az - bz;
    const float l2 = x*x + y*y + z*z;
    const float rinv = (l2 > 0.0f) ? rsqrtf(l2) : 0.0f;   // r==0 -> u=0, r=0 (matches ref)
    const float r  = l2 * rinv;
    const float ux = x * rinv, uy = y * rinv, uz = z * rinv;

    float sh[9];
    sh[0] = 1.0f;
    sh[1] = ux;  sh[2] = uy;  sh[3] = uz;
    sh[4] = SQRT3 * ux * uz;
    sh[5] = SQRT3 * ux * uy;
    sh[6] = uy*uy - 0.5f * (ux*ux + uz*uz);
    sh[7] = SQRT3 * uy * uz;
    sh[8] = HALF_SQRT3 * (uz*uz - ux*ux);

    // smooth_finite_embed: step = 1/11, values v_i = (i+1)/11, d_i = r*11 - (i+1)
    // sus(d+1)*sus(1-d) = exp(-1/(1+d) - 1/(1-d)) = exp(-2/(1-d^2)) when |d|<1, else 0.
    const float t = r * 11.0f;
    float emb[10];
#pragma unroll
    for (int i = 0; i < 10; i++) {
        const float dd = t - (float)(i + 1);
        const float g  = 1.0f - dd * dd;
        float f = 0.0f;
        if (g > 0.0f) f = PREF * __expf(__fdividef(-2.0f, g));
        emb[i] = f;
    }

    // Stage to shared memory (per-warp), then fully coalesced 128B stores.
#pragma unroll
    for (int k = 0; k < 9; k++)  ssh [w][lane * 9  + k] = sh[k];
#pragma unroll
    for (int k = 0; k < 10; k++) semb[w][lane * 11 + k] = emb[k];
    __syncwarp();

    const int e0 = e & ~31;  // warp's base edge
    if (e0 + 32 <= n) {
        float* po = out_sh + (size_t)e0 * 9;
#pragma unroll
        for (int i = 0; i < 9; i++)
            po[i * 32 + lane] = ssh[w][i * 32 + lane];

        float* pe = out_emb + (size_t)e0 * 10;
#pragma unroll
        for (int i = 0; i < 10; i++) {
            const int j = i * 32 + lane;            // flat idx within warp's 320 outputs
            pe[j] = semb[w][(j / 10) * 11 + (j % 10)];
        }
    } else if (valid) {
        // Partial tail warp: scalar stores.
#pragma unroll
        for (int k = 0; k < 9; k++)  out_sh [(size_t)e * 9  + k] = sh[k];
#pragma unroll
        for (int k = 0; k < 10; k++) out_emb[(size_t)e * 10 + k] = emb[k];
    }
}

extern "C" void kernel_launch(void* const* d_in, const int* in_sizes, int n_in,
                              void* d_out, int out_size)
{
    const float* pos  = (const float*)d_in[0];
    const float* qpos = (const float*)d_in[1];
    const int*   esrc = (const int*)  d_in[2];
    const int*   edst = (const int*)  d_in[3];

    const int npos = in_sizes[0] / 3;
    const int nq   = in_sizes[1] / 3;
    const int n    = in_sizes[2];
    if (n <= 0) return;

    float* out_sh  = (float*)d_out;
    float* out_emb = out_sh + (size_t)n * 9;

    const int blocks = (n + 255) / 256;

    if (npos <= POS_CAP && nq <= Q_CAP) {
        pad_q_kernel  <<<(nq   + 255) / 256, 256>>>(qpos, nq);
        pad_pos_kernel<<<(npos + 255) / 256, 256>>>(pos,  npos);
        edge_kernel<true><<<blocks, 256>>>(qpos, pos, esrc, edst, out_sh, out_emb, n);
    } else {
        edge_kernel<false><<<blocks, 256>>>(qpos, pos, esrc, edst, out_sh, out_emb, n);
    }
}

// round 13
// speedup vs baseline: 1.0181x; 1.0181x over previous
#include <cuda_runtime.h>
#include <cstdint>

// ---------------------------------------------------------------------------
// QuerySHLayerDeprecated: per-edge spherical harmonics (lmax=2) + smooth
// finite radial embedding (10 basis).
//
// Inputs (metadata order):
//   d_in[0] pos        float32 [100000, 3]
//   d_in[1] query_pos  float32 [8, 1250, 3]  (flattened to [10000, 3])
//   d_in[2] edge_src   int32   [E]  (indexes query rows)
//   d_in[3] edge_dst   int32   [E]  (indexes pos rows)
// Output: concat(edge_sh [E,9], edge_length_embedded [E,10]) as float32.
// ---------------------------------------------------------------------------

#define Q_CAP   10000
#define POS_CAP 100000

// Padded gather tables (float4 rows -> 1 LDG / 1 L2 sector per gather).
static __device__ float4 g_q4[Q_CAP];
static __device__ float4 g_pos4[POS_CAP];

__global__ void pad_q_kernel(const float* __restrict__ s, int rows) {
    int i = blockIdx.x * blockDim.x + threadIdx.x;
    if (i < rows) g_q4[i] = make_float4(s[3*i+0], s[3*i+1], s[3*i+2], 0.0f);
}
__global__ void pad_pos_kernel(const float* __restrict__ s, int rows) {
    int i = blockIdx.x * blockDim.x + threadIdx.x;
    if (i < rows) g_pos4[i] = make_float4(s[3*i+0], s[3*i+1], s[3*i+2], 0.0f);
}

template<bool PAD>
__global__ __launch_bounds__(256, 8)
void edge_kernel(const float* __restrict__ qraw, const float* __restrict__ praw,
                 const int* __restrict__ esrc, const int* __restrict__ edst,
                 float* __restrict__ out_sh, float* __restrict__ out_emb, int n)
{
    const float SQRT3      = 1.7320508075688772f;
    const float HALF_SQRT3 = 0.8660254037844386f;
    // 1.14136 * e^2 * sqrt(10)
    const float PREF = 1.14136f * 7.389056098930650f * 3.1622776601683795f;

    // Per-warp staging buffers for coalesced output stores.
    __shared__ float ssh [8][9 * 32];       // stride 9: gcd(9,32)=1, conflict-free
    __shared__ float semb[8][11 * 32];      // padded stride 11: conflict-free writes

    const int tid  = threadIdx.x;
    const int lane = tid & 31;
    const int w    = tid >> 5;
    const int e    = blockIdx.x * 256 + tid;
    const bool valid = e < n;

    float ax = 0.f, ay = 0.f, az = 0.f, bx = 0.f, by = 0.f, bz = 0.f;
    if (valid) {
        int s = __ldg(esrc + e);
        int d = __ldg(edst + e);
        if (PAD) {
            float4 a = __ldg(&g_q4[s]);
            float4 b = __ldg(&g_pos4[d]);
            ax = a.x; ay = a.y; az = a.z;
            bx = b.x; by = b.y; bz = b.z;
        } else {
            ax = __ldg(qraw + 3*s);  ay = __ldg(qraw + 3*s + 1); az = __ldg(qraw + 3*s + 2);
            bx = __ldg(praw + 3*d);  by = __ldg(praw + 3*d + 1); bz = __ldg(praw + 3*d + 2);
        }
    }

    const float x = ax - bx, y = ay - by, z = az - bz;
    const float l2 = x*x + y*y + z*z;
    const float rinv = (l2 > 0.0f) ? rsqrtf(l2) : 0.0f;   // r==0 -> u=0, r=0 (matches ref)
    const float r  = l2 * rinv;
    const float ux = x * rinv, uy = y * rinv, uz = z * rinv;

    float sh[9];
    sh[0] = 1.0f;
    sh[1] = ux;  sh[2] = uy;  sh[3] = uz;
    sh[4] = SQRT3 * ux * uz;
    sh[5] = SQRT3 * ux * uy;
    sh[6] = uy*uy - 0.5f * (ux*ux + uz*uz);
    sh[7] = SQRT3 * uy * uz;
    sh[8] = HALF_SQRT3 * (uz*uz - ux*ux);

    // smooth_finite_embed: step = 1/11, values v_i = (i+1)/11, d_i = r*11 - (i+1)
    // sus(d+1)*sus(1-d) = exp(-1/(1+d) - 1/(1-d)) = exp(-2/(1-d^2)) when |d|<1, else 0.
    const float t = r * 11.0f;
    float emb[10];
#pragma unroll
    for (int i = 0; i < 10; i++) {
        const float dd = t - (float)(i + 1);
        const float g  = 1.0f - dd * dd;
        float f = 0.0f;
        if (g > 0.0f) f = PREF * __expf(__fdividef(-2.0f, g));
        emb[i] = f;
    }

    // Stage to shared memory (per-warp), then fully coalesced 128B stores.
#pragma unroll
    for (int k = 0; k < 9; k++)  ssh [w][lane * 9  + k] = sh[k];
#pragma unroll
    for (int k = 0; k < 10; k++) semb[w][lane * 11 + k] = emb[k];
    __syncwarp();

    const int e0 = e & ~31;  // warp's base edge
    if (e0 + 32 <= n) {
        float* po = out_sh + (size_t)e0 * 9;
#pragma unroll
        for (int i = 0; i < 9; i++)
            po[i * 32 + lane] = ssh[w][i * 32 + lane];

        float* pe = out_emb + (size_t)e0 * 10;
#pragma unroll
        for (int i = 0; i < 10; i++) {
            const int j = i * 32 + lane;            // flat idx within warp's 320 outputs
            pe[j] = semb[w][(j / 10) * 11 + (j % 10)];
        }
    } else if (valid) {
        // Partial tail warp: scalar stores.
#pragma unroll
        for (int k = 0; k < 9; k++)  out_sh [(size_t)e * 9  + k] = sh[k];
#pragma unroll
        for (int k = 0; k < 10; k++) out_emb[(size_t)e * 10 + k] = emb[k];
    }
}

extern "C" void kernel_launch(void* const* d_in, const int* in_sizes, int n_in,
                              void* d_out, int out_size)
{
    const float* pos  = (const float*)d_in[0];
    const float* qpos = (const float*)d_in[1];
    const int*   esrc = (const int*)  d_in[2];
    const int*   edst = (const int*)  d_in[3];

    const int npos = in_sizes[0] / 3;
    const int nq   = in_sizes[1] / 3;
    const int n    = in_sizes[2];
    if (n <= 0) return;

    float* out_sh  = (float*)d_out;
    float* out_emb = out_sh + (size_t)n * 9;

    const int blocks = (n + 255) / 256;

    if (npos <= POS_CAP && nq <= Q_CAP) {
        pad_q_kernel  <<<(nq   + 255) / 256, 256>>>(qpos, nq);
        pad_pos_kernel<<<(npos + 255) / 256, 256>>>(pos,  npos);
        edge_kernel<true><<<blocks, 256>>>(qpos, pos, esrc, edst, out_sh, out_emb, n);
    } else {
        edge_kernel<false><<<blocks, 256>>>(qpos, pos, esrc, edst, out_sh, out_emb, n);
    }
}